// round 9
// baseline (speedup 1.0000x reference)
#include <cuda_runtime.h>
#include <cuda_bf16.h>
#include <cstdint>

#define BB    64
#define NNODE 1024
#define IND   512
#define HIDD  1024
#define LATD  256
#define TOK   (BB * NNODE)   // 65536

// ---------------------------------------------------------------------------
// Scratch (device globals — allocation is forbidden)
// ---------------------------------------------------------------------------
__device__ float g_d[TOK];
__device__ __align__(16) __nv_bfloat16 g_ahi[(size_t)BB * NNODE * NNODE];
__device__ __align__(16) __nv_bfloat16 g_alo[(size_t)BB * NNODE * NNODE];
__device__ __align__(16) __nv_bfloat16 g_xthi[(size_t)BB * IND * NNODE];
__device__ __align__(16) __nv_bfloat16 g_xtlo[(size_t)BB * IND * NNODE];
__device__ __align__(16) __nv_bfloat16 g_hhi[(size_t)TOK * IND];
__device__ __align__(16) __nv_bfloat16 g_hlo[(size_t)TOK * IND];
__device__ __align__(16) __nv_bfloat16 g_h1hi[(size_t)TOK * HIDD];
__device__ __align__(16) __nv_bfloat16 g_h1lo[(size_t)TOK * HIDD];
__device__ __align__(16) __nv_bfloat16 g_w1hi[HIDD * IND],  g_w1lo[HIDD * IND];
__device__ __align__(16) __nv_bfloat16 g_wcathi[2 * LATD * HIDD];   // [Wmu; Wlv]
__device__ __align__(16) __nv_bfloat16 g_wcatlo[2 * LATD * HIDD];

// ---------------------------------------------------------------------------
// helpers (baseline PTX only)
// ---------------------------------------------------------------------------
__device__ __forceinline__ uint32_t smem_u32(const void* p) {
    uint32_t a;
    asm("{ .reg .u64 t; cvta.to.shared.u64 t, %1; cvt.u32.u64 %0, t; }" : "=r"(a) : "l"(p));
    return a;
}
__device__ __forceinline__ void ldsm4(uint32_t addr, uint32_t* r) {
    asm volatile("ldmatrix.sync.aligned.m8n8.x4.shared.b16 {%0,%1,%2,%3}, [%4];"
                 : "=r"(r[0]), "=r"(r[1]), "=r"(r[2]), "=r"(r[3]) : "r"(addr));
}
__device__ __forceinline__ void mma16816(float* c, const uint32_t* a, const uint32_t* b) {
    asm volatile(
        "mma.sync.aligned.m16n8k16.row.col.f32.bf16.bf16.f32 "
        "{%0,%1,%2,%3}, {%4,%5,%6,%7}, {%8,%9}, {%0,%1,%2,%3};"
        : "+f"(c[0]), "+f"(c[1]), "+f"(c[2]), "+f"(c[3])
        : "r"(a[0]), "r"(a[1]), "r"(a[2]), "r"(a[3]), "r"(b[0]), "r"(b[1]));
}
__device__ __forceinline__ void cpasync16(uint32_t dst, const void* src) {
    asm volatile("cp.async.cg.shared.global [%0], [%1], 16;" :: "r"(dst), "l"(src) : "memory");
}
#define CP_COMMIT() asm volatile("cp.async.commit_group;" ::: "memory")
#define CP_WAIT0()  asm volatile("cp.async.wait_group 0;" ::: "memory")
#define CP_WAIT1()  asm volatile("cp.async.wait_group 1;" ::: "memory")

// ---------------------------------------------------------------------------
// Fused: a -> (hi, lo) split AND degree d = rsqrt(rowsum + 1 + 1e-8)
// ---------------------------------------------------------------------------
__global__ void __launch_bounds__(256) dsplit_a_kernel(const float* __restrict__ a) {
    int warp = (blockIdx.x * 256 + threadIdx.x) >> 5;
    int lane = threadIdx.x & 31;
    const float4* row = (const float4*)(a + (size_t)warp * NNODE);
    __nv_bfloat162* hi = (__nv_bfloat162*)(g_ahi + (size_t)warp * NNODE);
    __nv_bfloat162* lo = (__nv_bfloat162*)(g_alo + (size_t)warp * NNODE);
    float s = 0.f;
#pragma unroll
    for (int j = 0; j < 8; j++) {
        int i4 = lane + j * 32;
        float4 v = row[i4];
        s += v.x + v.y + v.z + v.w;
        float f[4] = {v.x, v.y, v.z, v.w};
        __nv_bfloat16 h[4], l[4];
#pragma unroll
        for (int k = 0; k < 4; k++) {
            h[k] = __float2bfloat16(f[k]);
            l[k] = __float2bfloat16(f[k] - __bfloat162float(h[k]));
        }
        hi[2 * i4]     = __nv_bfloat162(h[0], h[1]);
        hi[2 * i4 + 1] = __nv_bfloat162(h[2], h[3]);
        lo[2 * i4]     = __nv_bfloat162(l[0], l[1]);
        lo[2 * i4 + 1] = __nv_bfloat162(l[2], l[3]);
    }
#pragma unroll
    for (int off = 16; off; off >>= 1) s += __shfl_xor_sync(0xffffffffu, s, off);
    if (lane == 0) g_d[warp] = rsqrtf(s + 1.0f + 1e-8f);
}

// ---------------------------------------------------------------------------
// Kernel: xt[b,c,j] = d[b,j] * x[b,j,c]  transposed + split into hi/lo
// ---------------------------------------------------------------------------
__global__ void __launch_bounds__(256) split_xt_kernel(const float* __restrict__ x) {
    __shared__ float t[32][33];
    int b  = blockIdx.z;
    int j0 = blockIdx.y * 32;
    int c0 = blockIdx.x * 32;
    int tx = threadIdx.x, ty = threadIdx.y;      // (32, 8)
#pragma unroll
    for (int k = 0; k < 4; k++) {
        int j = j0 + ty + k * 8;
        float dv = g_d[b * NNODE + j];
        t[ty + k * 8][tx] = x[((size_t)(b * NNODE + j)) * IND + c0 + tx] * dv;
    }
    __syncthreads();
#pragma unroll
    for (int k = 0; k < 4; k++) {
        int c = c0 + ty + k * 8;
        int j = j0 + tx;
        float v = t[tx][ty + k * 8];
        __nv_bfloat16 h = __float2bfloat16(v);
        size_t o = ((size_t)b * IND + c) * NNODE + j;
        g_xthi[o] = h;
        g_xtlo[o] = __float2bfloat16(v - __bfloat162float(h));
    }
}

// ---------------------------------------------------------------------------
// All weight splits in one kernel
// ---------------------------------------------------------------------------
#define W1_F4   (HIDD * IND / 4)          // 131072
#define WHD_F4  (LATD * HIDD / 4)         // 65536
__global__ void __launch_bounds__(256) split_w_kernel(const float* __restrict__ W1,
                                                      const float* __restrict__ Wmu,
                                                      const float* __restrict__ Wlv) {
    size_t i = (size_t)blockIdx.x * 256 + threadIdx.x;
    const float* src; __nv_bfloat16 *hi, *lo; size_t o;
    if (i < W1_F4)                 { src = W1;  hi = g_w1hi;  lo = g_w1lo;  o = i; }
    else if (i < W1_F4 + WHD_F4)   { src = Wmu; hi = g_wcathi; lo = g_wcatlo; o = i - W1_F4; }
    else                           { src = Wlv; hi = g_wcathi + (size_t)LATD * HIDD;
                                     lo = g_wcatlo + (size_t)LATD * HIDD; o = i - W1_F4 - WHD_F4; }
    float4 v = ((const float4*)src)[o];
    float f[4] = {v.x, v.y, v.z, v.w};
    __nv_bfloat16 h[4], l[4];
#pragma unroll
    for (int k = 0; k < 4; k++) {
        h[k] = __float2bfloat16(f[k]);
        l[k] = __float2bfloat16(f[k] - __bfloat162float(h[k]));
    }
    ((__nv_bfloat162*)hi)[2 * o]     = __nv_bfloat162(h[0], h[1]);
    ((__nv_bfloat162*)hi)[2 * o + 1] = __nv_bfloat162(h[2], h[3]);
    ((__nv_bfloat162*)lo)[2 * o]     = __nv_bfloat162(l[0], l[1]);
    ((__nv_bfloat162*)lo)[2 * o + 1] = __nv_bfloat162(l[2], l[3]);
}

// ---------------------------------------------------------------------------
// Split-bf16 GEMM via mma.sync (HMMA): D[m,n] = sum_k A[m,k]*B[n,k]
//   3-term compensation: Ahi*Bhi + Ahi*Blo + Alo*Bhi  (fp32-equivalent)
// CTA tile 128x128, KC=32, 3-stage cp.async pipeline (R8), PLUS register
// double-buffering of B fragments: tnp+1's ldsm issued before tnp's MMAs.
// EPI: 0 = message passing (hi/lo out), 1 = bias+relu (hi/lo out),
//      3 = dual-head bias (cols<256 -> mu else logvar), fp32 out
// ---------------------------------------------------------------------------
#define TILE_B 8192
#define BUF_B  32768
#define GEMM_SMEM 98304
#define STG_STRIDE 272      // (128+8) bf16 per row (epilogue restage)

template <int KDIM, int EPI, int LDO>
__global__ void __launch_bounds__(256, 2) gemm_k(
    const __nv_bfloat16* __restrict__ Ahi, const __nv_bfloat16* __restrict__ Alo,
    const __nv_bfloat16* __restrict__ Bhi, const __nv_bfloat16* __restrict__ Blo,
    long bstride,
    float* __restrict__ outf,
    __nv_bfloat16* __restrict__ ohi, __nv_bfloat16* __restrict__ olo,
    const float* __restrict__ bias, const float* __restrict__ bias2,
    const float* __restrict__ xdiag)
{
    extern __shared__ char smem_raw[];
    const uint32_t sb  = smem_u32(smem_raw);
    const int tid  = threadIdx.x;
    const int wid  = tid >> 5;
    const int lane = tid & 31;
    const int n0   = blockIdx.x * 128;
    const int m0   = blockIdx.y * 128;
    const int wm   = wid & 3;       // 4 warps in M (32 rows)
    const int wn   = wid >> 2;      // 2 warps in N (64 cols)

    const long batch = bstride ? (long)(m0 >> 10) : 0;
    const __nv_bfloat16* srcA[2] = {Ahi, Alo};
    const __nv_bfloat16* srcB[2] = {Bhi + batch * bstride, Blo + batch * bstride};

    float acc[2][8][4];
#pragma unroll
    for (int i = 0; i < 2; i++)
#pragma unroll
        for (int j = 0; j < 8; j++)
#pragma unroll
            for (int k = 0; k < 4; k++) acc[i][j][k] = 0.f;

    // ldmatrix per-lane constants (swizzle folded per lane)
    const int a_row  = wm * 32 + (lane & 15);
    const int a_sw0  = ((lane >> 4) + (a_row >> 1)) & 3;     // seg at ks=0
    const uint32_t a_base = (uint32_t)(a_row * 64);
    const int b_row  = wn * 64 + ((lane >> 4) << 3) + (lane & 7);
    const int b_sw0  = (((lane >> 3) & 1) + (b_row >> 1)) & 3;
    const uint32_t b_base = (uint32_t)(b_row * 64);

    const int NC = KDIM / 32;

    auto stage = [&](int kk, uint32_t buf) {
#pragma unroll
        for (int i = 0; i < 4; i++) {          // A tiles (hi,lo)
            int idx  = i * 256 + tid;
            int tile = idx >> 9;
            int row  = (idx >> 2) & 127;
            int seg  = idx & 3;
            uint32_t sw = (uint32_t)(((seg + (row >> 1)) & 3) << 4);
            cpasync16(buf + tile * TILE_B + row * 64 + sw,
                      srcA[tile] + (size_t)(m0 + row) * KDIM + kk + seg * 8);
        }
#pragma unroll
        for (int i = 0; i < 4; i++) {          // B tiles (hi,lo)
            int idx  = i * 256 + tid;
            int tile = idx >> 9;
            int row  = (idx >> 2) & 127;
            int seg  = idx & 3;
            uint32_t sw = (uint32_t)(((seg + (row >> 1)) & 3) << 4);
            cpasync16(buf + 2 * TILE_B + tile * TILE_B + row * 64 + sw,
                      srcB[tile] + (size_t)(n0 + row) * KDIM + kk + seg * 8);
        }
        CP_COMMIT();
    };

    // prologue: two chunks in flight
    stage(0, sb);
    if (NC > 1) stage(32, sb + BUF_B);

    int bufidx = 0;
    for (int t = 0; t < NC; t++) {
        if (t == NC - 1) { CP_WAIT0(); } else { CP_WAIT1(); }
        __syncthreads();

        if (t + 2 < NC) {
            int nb = bufidx + 2; if (nb >= 3) nb -= 3;
            stage((t + 2) * 32, sb + (uint32_t)nb * BUF_B);
        }

        const uint32_t base = sb + (uint32_t)bufidx * BUF_B;
        if (++bufidx == 3) bufidx = 0;

#pragma unroll
        for (int ks = 0; ks < 2; ks++) {
            const uint32_t aswk = (uint32_t)(((a_sw0 + ks * 2) & 3) << 4);
            const uint32_t bswk = (uint32_t)(((b_sw0 + ks * 2) & 3) << 4);
            uint32_t ah[2][4], al[2][4];
#pragma unroll
            for (int tm = 0; tm < 2; tm++) {
                ldsm4(base + a_base + tm * 1024 + aswk, ah[tm]);
                ldsm4(base + TILE_B + a_base + tm * 1024 + aswk, al[tm]);
            }
            // B fragments double-buffered in registers: load tnp+1 before
            // issuing tnp's MMAs, so every ldsm has ~12 MMA slots to land.
            uint32_t bh[2][4], bl[2][4];
            ldsm4(base + 2 * TILE_B + b_base + bswk, bh[0]);
            ldsm4(base + 3 * TILE_B + b_base + bswk, bl[0]);
#pragma unroll
            for (int tnp = 0; tnp < 4; tnp++) {
                const int cur = tnp & 1, nxt = cur ^ 1;
                if (tnp < 3) {
                    ldsm4(base + 2 * TILE_B + b_base + (tnp + 1) * 1024 + bswk, bh[nxt]);
                    ldsm4(base + 3 * TILE_B + b_base + (tnp + 1) * 1024 + bswk, bl[nxt]);
                }
#pragma unroll
                for (int tm = 0; tm < 2; tm++)
#pragma unroll
                    for (int hf = 0; hf < 2; hf++)
                        mma16816(acc[tm][tnp * 2 + hf], ah[tm], bh[cur] + hf * 2);
#pragma unroll
                for (int tm = 0; tm < 2; tm++)
#pragma unroll
                    for (int hf = 0; hf < 2; hf++)
                        mma16816(acc[tm][tnp * 2 + hf], ah[tm], bl[cur] + hf * 2);
#pragma unroll
                for (int tm = 0; tm < 2; tm++)
#pragma unroll
                    for (int hf = 0; hf < 2; hf++)
                        mma16816(acc[tm][tnp * 2 + hf], al[tm], bh[cur] + hf * 2);
            }
        }
    }

    if (EPI == 3) {
#pragma unroll
        for (int tm = 0; tm < 2; tm++)
#pragma unroll
            for (int hf = 0; hf < 2; hf++) {
                const int row = m0 + wm * 32 + tm * 16 + hf * 8 + (lane >> 2);
#pragma unroll
                for (int tn = 0; tn < 8; tn++) {
                    const int col = n0 + wn * 64 + tn * 8 + (lane & 3) * 2;
                    float v0 = acc[tm][tn][hf * 2 + 0];
                    float v1 = acc[tm][tn][hf * 2 + 1];
                    const float* bp = (col < LATD) ? (bias + col) : (bias2 + col - LATD);
                    float2 bv = *(const float2*)bp;
                    v0 += bv.x; v1 += bv.y;
                    float* dst = (col < LATD)
                        ? (outf + (size_t)row * LATD + col)
                        : (outf + (size_t)TOK * LATD + (size_t)row * LATD + (col - LATD));
                    *(float2*)dst = make_float2(v0, v1);
                }
            }
        return;
    }

    // EPI 0/1: epilogue math, SMEM restage, 16B/lane global stores
    __syncthreads();
    char* hi_st = smem_raw;                 // 128 * 272 = 34816
    char* lo_st = smem_raw + 49152;
#pragma unroll
    for (int tm = 0; tm < 2; tm++) {
#pragma unroll
        for (int hf = 0; hf < 2; hf++) {
            const int rl = wm * 32 + tm * 16 + hf * 8 + (lane >> 2);
            const int row = m0 + rl;
            float di = 0.f, d2 = 0.f;
            if (EPI == 0) { di = g_d[row]; d2 = di * di; }
#pragma unroll
            for (int tn = 0; tn < 8; tn++) {
                const int cl = wn * 64 + tn * 8 + (lane & 3) * 2;
                float v0 = acc[tm][tn][hf * 2 + 0];
                float v1 = acc[tm][tn][hf * 2 + 1];
                if (EPI == 0) {
                    float2 xv = *(const float2*)(xdiag + (size_t)row * LDO + n0 + cl);
                    v0 = di * v0 + d2 * xv.x;
                    v1 = di * v1 + d2 * xv.y;
                } else {
                    float2 bv = *(const float2*)(bias + n0 + cl);
                    v0 = fmaxf(v0 + bv.x, 0.f);
                    v1 = fmaxf(v1 + bv.y, 0.f);
                }
                __nv_bfloat16 h0 = __float2bfloat16(v0);
                __nv_bfloat16 h1 = __float2bfloat16(v1);
                *(__nv_bfloat162*)(hi_st + rl * STG_STRIDE + cl * 2) = __nv_bfloat162(h0, h1);
                *(__nv_bfloat162*)(lo_st + rl * STG_STRIDE + cl * 2) = __nv_bfloat162(
                    __float2bfloat16(v0 - __bfloat162float(h0)),
                    __float2bfloat16(v1 - __bfloat162float(h1)));
            }
        }
    }
    __syncthreads();
#pragma unroll
    for (int it = 0; it < 8; it++) {
        int lin = it * 256 + tid;
        int r   = lin >> 4;
        int c16 = lin & 15;
        uint4 vh = *(uint4*)(hi_st + r * STG_STRIDE + c16 * 16);
        uint4 vl = *(uint4*)(lo_st + r * STG_STRIDE + c16 * 16);
        size_t go = (size_t)(m0 + r) * LDO + n0 + c16 * 8;
        *(uint4*)(ohi + go) = vh;
        *(uint4*)(olo + go) = vl;
    }
}

// ---------------------------------------------------------------------------
extern "C" void kernel_launch(void* const* d_in, const int* in_sizes, int n_in,
                              void* d_out, int out_size) {
    const float* x   = (const float*)d_in[0];
    const float* a   = (const float*)d_in[1];
    const float* W1  = (const float*)d_in[2];
    const float* b1  = (const float*)d_in[3];
    const float* Wmu = (const float*)d_in[4];
    const float* bmu = (const float*)d_in[5];
    const float* Wlv = (const float*)d_in[6];
    const float* blv = (const float*)d_in[7];
    float* out = (float*)d_out;

    cudaFuncSetAttribute(gemm_k<NNODE, 0, IND>,  cudaFuncAttributeMaxDynamicSharedMemorySize, GEMM_SMEM);
    cudaFuncSetAttribute(gemm_k<IND,   1, HIDD>, cudaFuncAttributeMaxDynamicSharedMemorySize, GEMM_SMEM);
    cudaFuncSetAttribute(gemm_k<HIDD,  3, LATD>, cudaFuncAttributeMaxDynamicSharedMemorySize, GEMM_SMEM);

    __nv_bfloat16 *ahi, *alo, *xthi, *xtlo, *hhi, *hlo, *h1hi, *h1lo;
    __nv_bfloat16 *w1hi, *w1lo, *wchi, *wclo;
    cudaGetSymbolAddress((void**)&ahi,  g_ahi);  cudaGetSymbolAddress((void**)&alo,  g_alo);
    cudaGetSymbolAddress((void**)&xthi, g_xthi); cudaGetSymbolAddress((void**)&xtlo, g_xtlo);
    cudaGetSymbolAddress((void**)&hhi,  g_hhi);  cudaGetSymbolAddress((void**)&hlo,  g_hlo);
    cudaGetSymbolAddress((void**)&h1hi, g_h1hi); cudaGetSymbolAddress((void**)&h1lo, g_h1lo);
    cudaGetSymbolAddress((void**)&w1hi, g_w1hi); cudaGetSymbolAddress((void**)&w1lo, g_w1lo);
    cudaGetSymbolAddress((void**)&wchi, g_wcathi); cudaGetSymbolAddress((void**)&wclo, g_wcatlo);

    // #1 fused adjacency split + degree factors
    dsplit_a_kernel<<<TOK / 8, 256>>>(a);
    // #2 x transpose + d_j scale + split
    split_xt_kernel<<<dim3(IND / 32, NNODE / 32, BB), dim3(32, 8)>>>(x);
    // #3 all weight splits
    split_w_kernel<<<(W1_F4 + 2 * WHD_F4) / 256, 256>>>(W1, Wmu, Wlv);
    // #4 message passing GEMM (profiled launch)
    gemm_k<NNODE, 0, IND><<<dim3(IND / 128, TOK / 128), 256, GEMM_SMEM>>>(
        ahi, alo, xthi, xtlo, (long)IND * NNODE, nullptr, hhi, hlo, nullptr, nullptr, x);
    // #5 h1 = relu(h @ W1^T + b1)
    gemm_k<IND, 1, HIDD><<<dim3(HIDD / 128, TOK / 128), 256, GEMM_SMEM>>>(
        hhi, hlo, w1hi, w1lo, 0, nullptr, h1hi, h1lo, b1, nullptr, nullptr);
    // #6 fused mu+logvar heads: one N=512 GEMM over [Wmu; Wlv]
    gemm_k<HIDD, 3, LATD><<<dim3((2 * LATD) / 128, TOK / 128), 256, GEMM_SMEM>>>(
        h1hi, h1lo, wchi, wclo, 0, out, nullptr, nullptr, bmu, blv, nullptr);
}

// round 10
// speedup vs baseline: 1.4469x; 1.4469x over previous
#include <cuda_runtime.h>
#include <cuda_fp16.h>
#include <cstdint>

#define BB    64
#define NNODE 1024
#define IND   512
#define HIDD  1024
#define LATD  256
#define TOK   (BB * NNODE)   // 65536

// ---------------------------------------------------------------------------
// Scratch (device globals — allocation is forbidden)
// ---------------------------------------------------------------------------
__device__ float g_d[TOK];
__device__ __align__(16) __half g_ah[(size_t)BB * NNODE * NNODE];     // a, fp16
__device__ __align__(16) __half g_xthi[(size_t)BB * IND * NNODE];
__device__ __align__(16) __half g_xtlo[(size_t)BB * IND * NNODE];
__device__ __align__(16) __half g_h[(size_t)TOK * IND];               // single fp16
__device__ __align__(16) __half g_h1[(size_t)TOK * HIDD];             // single fp16
__device__ __align__(16) __half g_w1hi[HIDD * IND],  g_w1lo[HIDD * IND];
__device__ __align__(16) __half g_wcathi[2 * LATD * HIDD];            // [Wmu; Wlv]
__device__ __align__(16) __half g_wcatlo[2 * LATD * HIDD];

// ---------------------------------------------------------------------------
// helpers (baseline PTX only)
// ---------------------------------------------------------------------------
__device__ __forceinline__ uint32_t smem_u32(const void* p) {
    uint32_t a;
    asm("{ .reg .u64 t; cvta.to.shared.u64 t, %1; cvt.u32.u64 %0, t; }" : "=r"(a) : "l"(p));
    return a;
}
__device__ __forceinline__ void ldsm4(uint32_t addr, uint32_t* r) {
    asm volatile("ldmatrix.sync.aligned.m8n8.x4.shared.b16 {%0,%1,%2,%3}, [%4];"
                 : "=r"(r[0]), "=r"(r[1]), "=r"(r[2]), "=r"(r[3]) : "r"(addr));
}
__device__ __forceinline__ void mma16816(float* c, const uint32_t* a, const uint32_t* b) {
    asm volatile(
        "mma.sync.aligned.m16n8k16.row.col.f32.f16.f16.f32 "
        "{%0,%1,%2,%3}, {%4,%5,%6,%7}, {%8,%9}, {%0,%1,%2,%3};"
        : "+f"(c[0]), "+f"(c[1]), "+f"(c[2]), "+f"(c[3])
        : "r"(a[0]), "r"(a[1]), "r"(a[2]), "r"(a[3]), "r"(b[0]), "r"(b[1]));
}
__device__ __forceinline__ void cpasync16(uint32_t dst, const void* src) {
    asm volatile("cp.async.cg.shared.global [%0], [%1], 16;" :: "r"(dst), "l"(src) : "memory");
}
#define CP_COMMIT() asm volatile("cp.async.commit_group;" ::: "memory")
#define CP_WAIT0()  asm volatile("cp.async.wait_group 0;" ::: "memory")
#define CP_WAIT1()  asm volatile("cp.async.wait_group 1;" ::: "memory")

// ---------------------------------------------------------------------------
// Fused: a -> fp16 AND degree d = rsqrt(rowsum + 1 + 1e-8)
// ---------------------------------------------------------------------------
__global__ void __launch_bounds__(256) dsplit_a_kernel(const float* __restrict__ a) {
    int warp = (blockIdx.x * 256 + threadIdx.x) >> 5;
    int lane = threadIdx.x & 31;
    const float4* row = (const float4*)(a + (size_t)warp * NNODE);
    __half2* o = (__half2*)(g_ah + (size_t)warp * NNODE);
    float s = 0.f;
#pragma unroll
    for (int j = 0; j < 8; j++) {
        int i4 = lane + j * 32;
        float4 v = row[i4];
        s += v.x + v.y + v.z + v.w;
        o[2 * i4]     = __floats2half2_rn(v.x, v.y);
        o[2 * i4 + 1] = __floats2half2_rn(v.z, v.w);
    }
#pragma unroll
    for (int off = 16; off; off >>= 1) s += __shfl_xor_sync(0xffffffffu, s, off);
    if (lane == 0) g_d[warp] = rsqrtf(s + 1.0f + 1e-8f);
}

// ---------------------------------------------------------------------------
// Kernel: xt[b,c,j] = d[b,j] * x[b,j,c]  transposed + split into fp16 hi/lo
// ---------------------------------------------------------------------------
__global__ void __launch_bounds__(256) split_xt_kernel(const float* __restrict__ x) {
    __shared__ float t[32][33];
    int b  = blockIdx.z;
    int j0 = blockIdx.y * 32;
    int c0 = blockIdx.x * 32;
    int tx = threadIdx.x, ty = threadIdx.y;      // (32, 8)
#pragma unroll
    for (int k = 0; k < 4; k++) {
        int j = j0 + ty + k * 8;
        float dv = g_d[b * NNODE + j];
        t[ty + k * 8][tx] = x[((size_t)(b * NNODE + j)) * IND + c0 + tx] * dv;
    }
    __syncthreads();
#pragma unroll
    for (int k = 0; k < 4; k++) {
        int c = c0 + ty + k * 8;
        int j = j0 + tx;
        float v = t[tx][ty + k * 8];
        __half h = __float2half_rn(v);
        size_t o = ((size_t)b * IND + c) * NNODE + j;
        g_xthi[o] = h;
        g_xtlo[o] = __float2half_rn(v - __half2float(h));
    }
}

// ---------------------------------------------------------------------------
// All weight splits in one kernel (fp16 hi/lo)
// ---------------------------------------------------------------------------
#define W1_F4   (HIDD * IND / 4)          // 131072
#define WHD_F4  (LATD * HIDD / 4)         // 65536
__global__ void __launch_bounds__(256) split_w_kernel(const float* __restrict__ W1,
                                                      const float* __restrict__ Wmu,
                                                      const float* __restrict__ Wlv) {
    size_t i = (size_t)blockIdx.x * 256 + threadIdx.x;
    const float* src; __half *hi, *lo; size_t o;
    if (i < W1_F4)                 { src = W1;  hi = g_w1hi;  lo = g_w1lo;  o = i; }
    else if (i < W1_F4 + WHD_F4)   { src = Wmu; hi = g_wcathi; lo = g_wcatlo; o = i - W1_F4; }
    else                           { src = Wlv; hi = g_wcathi + (size_t)LATD * HIDD;
                                     lo = g_wcatlo + (size_t)LATD * HIDD; o = i - W1_F4 - WHD_F4; }
    float4 v = ((const float4*)src)[o];
    float f[4] = {v.x, v.y, v.z, v.w};
    __half h[4], l[4];
#pragma unroll
    for (int k = 0; k < 4; k++) {
        h[k] = __float2half_rn(f[k]);
        l[k] = __float2half_rn(f[k] - __half2float(h[k]));
    }
    ((__half2*)hi)[2 * o]     = __halves2half2(h[0], h[1]);
    ((__half2*)hi)[2 * o + 1] = __halves2half2(h[2], h[3]);
    ((__half2*)lo)[2 * o]     = __halves2half2(l[0], l[1]);
    ((__half2*)lo)[2 * o + 1] = __halves2half2(l[2], l[3]);
}

// ---------------------------------------------------------------------------
// 2-term fp16 GEMM via mma.sync (HMMA): D[m,n] = sum_k A[m,k]*B[n,k]
//   A single fp16;  B split hi/lo:  D = A*Bhi + A*Blo   (~2^-12 accurate)
// CTA tile 128x128, KC=32, 3-stage cp.async pipeline, swizzled 64B smem rows.
// SMEM per buffer: A@0 (8192), Bhi@8192, Blo@16384 -> 24576; 3 buffers.
// EPI: 0 = message passing (d_m scale + d_m^2*x diag, fp16 out)
//      1 = bias + relu (fp16 out)
//      3 = dual-head bias (cols<256 -> mu else logvar), fp32 out
// ---------------------------------------------------------------------------
#define TILE_B 8192
#define BUF_B  24576
#define GEMM_SMEM 73728
#define STG_STRIDE 272      // (128+8) fp16 per row (epilogue restage)

template <int KDIM, int EPI, int LDO>
__global__ void __launch_bounds__(256, 2) gemm_k(
    const __half* __restrict__ A,
    const __half* __restrict__ Bhi, const __half* __restrict__ Blo,
    long bstride,
    float* __restrict__ outf,
    __half* __restrict__ oh,
    const float* __restrict__ bias, const float* __restrict__ bias2,
    const float* __restrict__ xdiag)
{
    extern __shared__ char smem_raw[];
    const uint32_t sb  = smem_u32(smem_raw);
    const int tid  = threadIdx.x;
    const int wid  = tid >> 5;
    const int lane = tid & 31;
    const int n0   = blockIdx.x * 128;
    const int m0   = blockIdx.y * 128;
    const int wm   = wid & 3;       // 4 warps in M (32 rows)
    const int wn   = wid >> 2;      // 2 warps in N (64 cols)

    const long batch = bstride ? (long)(m0 >> 10) : 0;
    const __half* srcB[2] = {Bhi + batch * bstride, Blo + batch * bstride};

    float acc[2][8][4];
#pragma unroll
    for (int i = 0; i < 2; i++)
#pragma unroll
        for (int j = 0; j < 8; j++)
#pragma unroll
            for (int k = 0; k < 4; k++) acc[i][j][k] = 0.f;

    // ldmatrix per-lane constants (swizzle folded per lane)
    const int a_row  = wm * 32 + (lane & 15);
    const int a_sw0  = ((lane >> 4) + (a_row >> 1)) & 3;
    const uint32_t a_base = (uint32_t)(a_row * 64);
    const int b_row  = wn * 64 + ((lane >> 4) << 3) + (lane & 7);
    const int b_sw0  = (((lane >> 3) & 1) + (b_row >> 1)) & 3;
    const uint32_t b_base = (uint32_t)(b_row * 64);

    const int NC = KDIM / 32;

    auto stage = [&](int kk, uint32_t buf) {
        // A tile: 128 rows * 4 segs = 512
#pragma unroll
        for (int i = 0; i < 2; i++) {
            int idx  = i * 256 + tid;
            int row  = idx >> 2;
            int seg  = idx & 3;
            uint32_t sw = (uint32_t)(((seg + (row >> 1)) & 3) << 4);
            cpasync16(buf + row * 64 + sw,
                      A + (size_t)(m0 + row) * KDIM + kk + seg * 8);
        }
        // B tiles (hi,lo): 2 * 128 rows * 4 segs = 1024
#pragma unroll
        for (int i = 0; i < 4; i++) {
            int idx  = i * 256 + tid;
            int tile = idx >> 9;
            int row  = (idx >> 2) & 127;
            int seg  = idx & 3;
            uint32_t sw = (uint32_t)(((seg + (row >> 1)) & 3) << 4);
            cpasync16(buf + TILE_B + tile * TILE_B + row * 64 + sw,
                      srcB[tile] + (size_t)(n0 + row) * KDIM + kk + seg * 8);
        }
        CP_COMMIT();
    };

    // prologue: two chunks in flight
    stage(0, sb);
    if (NC > 1) stage(32, sb + BUF_B);

    int bufidx = 0;
    for (int t = 0; t < NC; t++) {
        if (t == NC - 1) { CP_WAIT0(); } else { CP_WAIT1(); }
        __syncthreads();

        if (t + 2 < NC) {
            int nb = bufidx + 2; if (nb >= 3) nb -= 3;
            stage((t + 2) * 32, sb + (uint32_t)nb * BUF_B);
        }

        const uint32_t base = sb + (uint32_t)bufidx * BUF_B;
        if (++bufidx == 3) bufidx = 0;

#pragma unroll
        for (int ks = 0; ks < 2; ks++) {
            const uint32_t aswk = (uint32_t)(((a_sw0 + ks * 2) & 3) << 4);
            const uint32_t bswk = (uint32_t)(((b_sw0 + ks * 2) & 3) << 4);
            uint32_t ah[2][4];
#pragma unroll
            for (int tm = 0; tm < 2; tm++)
                ldsm4(base + a_base + tm * 1024 + aswk, ah[tm]);
#pragma unroll
            for (int tnp = 0; tnp < 4; tnp++) {
                uint32_t bh[4], bl[4];
                ldsm4(base + TILE_B + b_base + tnp * 1024 + bswk, bh);
                ldsm4(base + 2 * TILE_B + b_base + tnp * 1024 + bswk, bl);
#pragma unroll
                for (int tm = 0; tm < 2; tm++)
#pragma unroll
                    for (int hf = 0; hf < 2; hf++)
                        mma16816(acc[tm][tnp * 2 + hf], ah[tm], bh + hf * 2);
#pragma unroll
                for (int tm = 0; tm < 2; tm++)
#pragma unroll
                    for (int hf = 0; hf < 2; hf++)
                        mma16816(acc[tm][tnp * 2 + hf], ah[tm], bl + hf * 2);
            }
        }
    }

    if (EPI == 3) {
#pragma unroll
        for (int tm = 0; tm < 2; tm++)
#pragma unroll
            for (int hf = 0; hf < 2; hf++) {
                const int row = m0 + wm * 32 + tm * 16 + hf * 8 + (lane >> 2);
#pragma unroll
                for (int tn = 0; tn < 8; tn++) {
                    const int col = n0 + wn * 64 + tn * 8 + (lane & 3) * 2;
                    float v0 = acc[tm][tn][hf * 2 + 0];
                    float v1 = acc[tm][tn][hf * 2 + 1];
                    const float* bp = (col < LATD) ? (bias + col) : (bias2 + col - LATD);
                    float2 bv = *(const float2*)bp;
                    v0 += bv.x; v1 += bv.y;
                    float* dst = (col < LATD)
                        ? (outf + (size_t)row * LATD + col)
                        : (outf + (size_t)TOK * LATD + (size_t)row * LATD + (col - LATD));
                    *(float2*)dst = make_float2(v0, v1);
                }
            }
        return;
    }

    // EPI 0/1: epilogue math, SMEM restage (single fp16), 16B/lane stores
    __syncthreads();
    char* st = smem_raw;                 // 128 * 272 = 34816 <= 73728
#pragma unroll
    for (int tm = 0; tm < 2; tm++) {
#pragma unroll
        for (int hf = 0; hf < 2; hf++) {
            const int rl = wm * 32 + tm * 16 + hf * 8 + (lane >> 2);
            const int row = m0 + rl;
            float di = 0.f, d2 = 0.f;
            if (EPI == 0) { di = g_d[row]; d2 = di * di; }
#pragma unroll
            for (int tn = 0; tn < 8; tn++) {
                const int cl = wn * 64 + tn * 8 + (lane & 3) * 2;
                float v0 = acc[tm][tn][hf * 2 + 0];
                float v1 = acc[tm][tn][hf * 2 + 1];
                if (EPI == 0) {
                    float2 xv = *(const float2*)(xdiag + (size_t)row * LDO + n0 + cl);
                    v0 = di * v0 + d2 * xv.x;
                    v1 = di * v1 + d2 * xv.y;
                } else {
                    float2 bv = *(const float2*)(bias + n0 + cl);
                    v0 = fmaxf(v0 + bv.x, 0.f);
                    v1 = fmaxf(v1 + bv.y, 0.f);
                }
                *(__half2*)(st + rl * STG_STRIDE + cl * 2) = __floats2half2_rn(v0, v1);
            }
        }
    }
    __syncthreads();
#pragma unroll
    for (int it = 0; it < 8; it++) {
        int lin = it * 256 + tid;        // 0..2047
        int r   = lin >> 4;              // 0..127
        int c16 = lin & 15;              // 16B segment (128 fp16 = 16 segs)
        uint4 v = *(uint4*)(st + r * STG_STRIDE + c16 * 16);
        *(uint4*)(oh + (size_t)(m0 + r) * LDO + n0 + c16 * 8) = v;
    }
}

// ---------------------------------------------------------------------------
extern "C" void kernel_launch(void* const* d_in, const int* in_sizes, int n_in,
                              void* d_out, int out_size) {
    const float* x   = (const float*)d_in[0];
    const float* a   = (const float*)d_in[1];
    const float* W1  = (const float*)d_in[2];
    const float* b1  = (const float*)d_in[3];
    const float* Wmu = (const float*)d_in[4];
    const float* bmu = (const float*)d_in[5];
    const float* Wlv = (const float*)d_in[6];
    const float* blv = (const float*)d_in[7];
    float* out = (float*)d_out;

    cudaFuncSetAttribute(gemm_k<NNODE, 0, IND>,  cudaFuncAttributeMaxDynamicSharedMemorySize, GEMM_SMEM);
    cudaFuncSetAttribute(gemm_k<IND,   1, HIDD>, cudaFuncAttributeMaxDynamicSharedMemorySize, GEMM_SMEM);
    cudaFuncSetAttribute(gemm_k<HIDD,  3, LATD>, cudaFuncAttributeMaxDynamicSharedMemorySize, GEMM_SMEM);

    __half *ah, *xthi, *xtlo, *h, *h1, *w1hi, *w1lo, *wchi, *wclo;
    cudaGetSymbolAddress((void**)&ah,   g_ah);
    cudaGetSymbolAddress((void**)&xthi, g_xthi); cudaGetSymbolAddress((void**)&xtlo, g_xtlo);
    cudaGetSymbolAddress((void**)&h,    g_h);    cudaGetSymbolAddress((void**)&h1,   g_h1);
    cudaGetSymbolAddress((void**)&w1hi, g_w1hi); cudaGetSymbolAddress((void**)&w1lo, g_w1lo);
    cudaGetSymbolAddress((void**)&wchi, g_wcathi); cudaGetSymbolAddress((void**)&wclo, g_wcatlo);

    // #1 adjacency -> fp16 + degree factors
    dsplit_a_kernel<<<TOK / 8, 256>>>(a);
    // #2 x transpose + d_j scale + fp16 hi/lo split
    split_xt_kernel<<<dim3(IND / 32, NNODE / 32, BB), dim3(32, 8)>>>(x);
    // #3 all weight splits
    split_w_kernel<<<(W1_F4 + 2 * WHD_F4) / 256, 256>>>(W1, Wmu, Wlv);
    // #4 message passing GEMM (profiled launch): h = a_norm @ x
    gemm_k<NNODE, 0, IND><<<dim3(IND / 128, TOK / 128), 256, GEMM_SMEM>>>(
        ah, xthi, xtlo, (long)IND * NNODE, nullptr, h, nullptr, nullptr, x);
    // #5 h1 = relu(h @ W1^T + b1)
    gemm_k<IND, 1, HIDD><<<dim3(HIDD / 128, TOK / 128), 256, GEMM_SMEM>>>(
        h, w1hi, w1lo, 0, nullptr, h1, b1, nullptr, nullptr);
    // #6 fused mu+logvar heads: one N=512 GEMM over [Wmu; Wlv]
    gemm_k<HIDD, 3, LATD><<<dim3((2 * LATD) / 128, TOK / 128), 256, GEMM_SMEM>>>(
        h1, wchi, wclo, 0, out, nullptr, bmu, blv, nullptr);
}

// round 11
// speedup vs baseline: 2.3368x; 1.6151x over previous
#include <cuda_runtime.h>
#include <cuda_fp16.h>
#include <cstdint>

#define BB    64
#define NNODE 1024
#define IND   512
#define HIDD  1024
#define LATD  256
#define TOK   (BB * NNODE)   // 65536

// ---------------------------------------------------------------------------
// Scratch (device globals — allocation is forbidden)
// ---------------------------------------------------------------------------
__device__ float g_d[TOK];
__device__ __align__(16) __half g_ah[(size_t)BB * NNODE * NNODE];   // a, fp16
__device__ __align__(16) __half g_xt[(size_t)BB * IND * NNODE];     // d_j * x^T
__device__ __align__(16) __half g_h[(size_t)TOK * IND];
__device__ __align__(16) __half g_h1[(size_t)TOK * HIDD];
__device__ __align__(16) __half g_w1[HIDD * IND];
__device__ __align__(16) __half g_wcat[2 * LATD * HIDD];            // [Wmu; Wlv]

// ---------------------------------------------------------------------------
// helpers (baseline PTX only)
// ---------------------------------------------------------------------------
__device__ __forceinline__ uint32_t smem_u32(const void* p) {
    uint32_t a;
    asm("{ .reg .u64 t; cvta.to.shared.u64 t, %1; cvt.u32.u64 %0, t; }" : "=r"(a) : "l"(p));
    return a;
}
__device__ __forceinline__ void ldsm4(uint32_t addr, uint32_t* r) {
    asm volatile("ldmatrix.sync.aligned.m8n8.x4.shared.b16 {%0,%1,%2,%3}, [%4];"
                 : "=r"(r[0]), "=r"(r[1]), "=r"(r[2]), "=r"(r[3]) : "r"(addr));
}
__device__ __forceinline__ void mma16816(float* c, const uint32_t* a, const uint32_t* b) {
    asm volatile(
        "mma.sync.aligned.m16n8k16.row.col.f32.f16.f16.f32 "
        "{%0,%1,%2,%3}, {%4,%5,%6,%7}, {%8,%9}, {%0,%1,%2,%3};"
        : "+f"(c[0]), "+f"(c[1]), "+f"(c[2]), "+f"(c[3])
        : "r"(a[0]), "r"(a[1]), "r"(a[2]), "r"(a[3]), "r"(b[0]), "r"(b[1]));
}
__device__ __forceinline__ void cpasync16(uint32_t dst, const void* src) {
    asm volatile("cp.async.cg.shared.global [%0], [%1], 16;" :: "r"(dst), "l"(src) : "memory");
}
#define CP_COMMIT() asm volatile("cp.async.commit_group;" ::: "memory")
#define CP_WAIT0()  asm volatile("cp.async.wait_group 0;" ::: "memory")
#define CP_WAIT1()  asm volatile("cp.async.wait_group 1;" ::: "memory")

// ---------------------------------------------------------------------------
// Fused: a -> fp16 AND degree d = rsqrt(rowsum + 1 + 1e-8)
// ---------------------------------------------------------------------------
__global__ void __launch_bounds__(256) dsplit_a_kernel(const float* __restrict__ a) {
    int warp = (blockIdx.x * 256 + threadIdx.x) >> 5;
    int lane = threadIdx.x & 31;
    const float4* row = (const float4*)(a + (size_t)warp * NNODE);
    __half2* o = (__half2*)(g_ah + (size_t)warp * NNODE);
    float s = 0.f;
#pragma unroll
    for (int j = 0; j < 8; j++) {
        int i4 = lane + j * 32;
        float4 v = row[i4];
        s += v.x + v.y + v.z + v.w;
        o[2 * i4]     = __floats2half2_rn(v.x, v.y);
        o[2 * i4 + 1] = __floats2half2_rn(v.z, v.w);
    }
#pragma unroll
    for (int off = 16; off; off >>= 1) s += __shfl_xor_sync(0xffffffffu, s, off);
    if (lane == 0) g_d[warp] = rsqrtf(s + 1.0f + 1e-8f);
}

// ---------------------------------------------------------------------------
// Kernel: xt[b,c,j] = fp16(d[b,j] * x[b,j,c])  (transposed)
// ---------------------------------------------------------------------------
__global__ void __launch_bounds__(256) split_xt_kernel(const float* __restrict__ x) {
    __shared__ float t[32][33];
    int b  = blockIdx.z;
    int j0 = blockIdx.y * 32;
    int c0 = blockIdx.x * 32;
    int tx = threadIdx.x, ty = threadIdx.y;      // (32, 8)
#pragma unroll
    for (int k = 0; k < 4; k++) {
        int j = j0 + ty + k * 8;
        float dv = g_d[b * NNODE + j];
        t[ty + k * 8][tx] = x[((size_t)(b * NNODE + j)) * IND + c0 + tx] * dv;
    }
    __syncthreads();
#pragma unroll
    for (int k = 0; k < 4; k++) {
        int c = c0 + ty + k * 8;
        int j = j0 + tx;
        g_xt[((size_t)b * IND + c) * NNODE + j] = __float2half_rn(t[tx][ty + k * 8]);
    }
}

// ---------------------------------------------------------------------------
// All weight conversions (single fp16) in one kernel
// ---------------------------------------------------------------------------
#define W1_F4   (HIDD * IND / 4)          // 131072
#define WHD_F4  (LATD * HIDD / 4)         // 65536
__global__ void __launch_bounds__(256) split_w_kernel(const float* __restrict__ W1,
                                                      const float* __restrict__ Wmu,
                                                      const float* __restrict__ Wlv) {
    size_t i = (size_t)blockIdx.x * 256 + threadIdx.x;
    const float* src; __half* dst; size_t o;
    if (i < W1_F4)                 { src = W1;  dst = g_w1;   o = i; }
    else if (i < W1_F4 + WHD_F4)   { src = Wmu; dst = g_wcat; o = i - W1_F4; }
    else                           { src = Wlv; dst = g_wcat + (size_t)LATD * HIDD;
                                     o = i - W1_F4 - WHD_F4; }
    float4 v = ((const float4*)src)[o];
    ((__half2*)dst)[2 * o]     = __floats2half2_rn(v.x, v.y);
    ((__half2*)dst)[2 * o + 1] = __floats2half2_rn(v.z, v.w);
}

// ---------------------------------------------------------------------------
// Pure fp16 GEMM via mma.sync (HMMA): D[m,n] = sum_k A[m,k]*B[n,k]
// CTA tile 128x128, KC=32, 3-stage cp.async pipeline, swizzled 64B smem rows.
// SMEM per buffer: A@0 (8192), B@8192 -> 16384; 3 buffers = 49152.
// EPI: 0 = message passing (d_m scale + d_m^2*x diag, fp16 out)
//      1 = bias + relu (fp16 out)
//      3 = dual-head bias (cols<256 -> mu else logvar), fp32 out
// ---------------------------------------------------------------------------
#define TILE_B 8192
#define BUF_B  16384
#define GEMM_SMEM 49152
#define STG_STRIDE 272      // (128+8) fp16 per row (epilogue restage)

template <int KDIM, int EPI, int LDO>
__global__ void __launch_bounds__(256, 2) gemm_k(
    const __half* __restrict__ A,
    const __half* __restrict__ B,
    long bstride,
    float* __restrict__ outf,
    __half* __restrict__ oh,
    const float* __restrict__ bias, const float* __restrict__ bias2,
    const float* __restrict__ xdiag)
{
    extern __shared__ char smem_raw[];
    const uint32_t sb  = smem_u32(smem_raw);
    const int tid  = threadIdx.x;
    const int wid  = tid >> 5;
    const int lane = tid & 31;
    const int n0   = blockIdx.x * 128;
    const int m0   = blockIdx.y * 128;
    const int wm   = wid & 3;       // 4 warps in M (32 rows)
    const int wn   = wid >> 2;      // 2 warps in N (64 cols)

    const __half* Bb = B + (bstride ? (long)(m0 >> 10) * bstride : 0);

    float acc[2][8][4];
#pragma unroll
    for (int i = 0; i < 2; i++)
#pragma unroll
        for (int j = 0; j < 8; j++)
#pragma unroll
            for (int k = 0; k < 4; k++) acc[i][j][k] = 0.f;

    // ldmatrix per-lane constants (swizzle folded per lane)
    const int a_row  = wm * 32 + (lane & 15);
    const int a_sw0  = ((lane >> 4) + (a_row >> 1)) & 3;
    const uint32_t a_base = (uint32_t)(a_row * 64);
    const int b_row  = wn * 64 + ((lane >> 4) << 3) + (lane & 7);
    const int b_sw0  = (((lane >> 3) & 1) + (b_row >> 1)) & 3;
    const uint32_t b_base = (uint32_t)(b_row * 64);

    const int NC = KDIM / 32;

    auto stage = [&](int kk, uint32_t buf) {
        // A tile: 128 rows * 4 segs = 512
#pragma unroll
        for (int i = 0; i < 2; i++) {
            int idx  = i * 256 + tid;
            int row  = idx >> 2;
            int seg  = idx & 3;
            uint32_t sw = (uint32_t)(((seg + (row >> 1)) & 3) << 4);
            cpasync16(buf + row * 64 + sw,
                      A + (size_t)(m0 + row) * KDIM + kk + seg * 8);
        }
        // B tile: 128 rows * 4 segs = 512
#pragma unroll
        for (int i = 0; i < 2; i++) {
            int idx  = i * 256 + tid;
            int row  = idx >> 2;
            int seg  = idx & 3;
            uint32_t sw = (uint32_t)(((seg + (row >> 1)) & 3) << 4);
            cpasync16(buf + TILE_B + row * 64 + sw,
                      Bb + (size_t)(n0 + row) * KDIM + kk + seg * 8);
        }
        CP_COMMIT();
    };

    // prologue: two chunks in flight
    stage(0, sb);
    if (NC > 1) stage(32, sb + BUF_B);

    int bufidx = 0;
    for (int t = 0; t < NC; t++) {
        if (t == NC - 1) { CP_WAIT0(); } else { CP_WAIT1(); }
        __syncthreads();

        if (t + 2 < NC) {
            int nb = bufidx + 2; if (nb >= 3) nb -= 3;
            stage((t + 2) * 32, sb + (uint32_t)nb * BUF_B);
        }

        const uint32_t base = sb + (uint32_t)bufidx * BUF_B;
        if (++bufidx == 3) bufidx = 0;

#pragma unroll
        for (int ks = 0; ks < 2; ks++) {
            const uint32_t aswk = (uint32_t)(((a_sw0 + ks * 2) & 3) << 4);
            const uint32_t bswk = (uint32_t)(((b_sw0 + ks * 2) & 3) << 4);
            uint32_t ah[2][4];
#pragma unroll
            for (int tm = 0; tm < 2; tm++)
                ldsm4(base + a_base + tm * 1024 + aswk, ah[tm]);
#pragma unroll
            for (int tnp = 0; tnp < 4; tnp++) {
                uint32_t bh[4];
                ldsm4(base + TILE_B + b_base + tnp * 1024 + bswk, bh);
#pragma unroll
                for (int tm = 0; tm < 2; tm++)
#pragma unroll
                    for (int hf = 0; hf < 2; hf++)
                        mma16816(acc[tm][tnp * 2 + hf], ah[tm], bh + hf * 2);
            }
        }
    }

    if (EPI == 3) {
#pragma unroll
        for (int tm = 0; tm < 2; tm++)
#pragma unroll
            for (int hf = 0; hf < 2; hf++) {
                const int row = m0 + wm * 32 + tm * 16 + hf * 8 + (lane >> 2);
#pragma unroll
                for (int tn = 0; tn < 8; tn++) {
                    const int col = n0 + wn * 64 + tn * 8 + (lane & 3) * 2;
                    float v0 = acc[tm][tn][hf * 2 + 0];
                    float v1 = acc[tm][tn][hf * 2 + 1];
                    const float* bp = (col < LATD) ? (bias + col) : (bias2 + col - LATD);
                    float2 bv = *(const float2*)bp;
                    v0 += bv.x; v1 += bv.y;
                    float* dst = (col < LATD)
                        ? (outf + (size_t)row * LATD + col)
                        : (outf + (size_t)TOK * LATD + (size_t)row * LATD + (col - LATD));
                    *(float2*)dst = make_float2(v0, v1);
                }
            }
        return;
    }

    // EPI 0/1: epilogue math, SMEM restage (fp16), 16B/lane stores
    __syncthreads();
    char* st = smem_raw;                 // 128 * 272 = 34816 <= 49152
#pragma unroll
    for (int tm = 0; tm < 2; tm++) {
#pragma unroll
        for (int hf = 0; hf < 2; hf++) {
            const int rl = wm * 32 + tm * 16 + hf * 8 + (lane >> 2);
            const int row = m0 + rl;
            float di = 0.f, d2 = 0.f;
            if (EPI == 0) { di = g_d[row]; d2 = di * di; }
#pragma unroll
            for (int tn = 0; tn < 8; tn++) {
                const int cl = wn * 64 + tn * 8 + (lane & 3) * 2;
                float v0 = acc[tm][tn][hf * 2 + 0];
                float v1 = acc[tm][tn][hf * 2 + 1];
                if (EPI == 0) {
                    float2 xv = *(const float2*)(xdiag + (size_t)row * LDO + n0 + cl);
                    v0 = di * v0 + d2 * xv.x;
                    v1 = di * v1 + d2 * xv.y;
                } else {
                    float2 bv = *(const float2*)(bias + n0 + cl);
                    v0 = fmaxf(v0 + bv.x, 0.f);
                    v1 = fmaxf(v1 + bv.y, 0.f);
                }
                *(__half2*)(st + rl * STG_STRIDE + cl * 2) = __floats2half2_rn(v0, v1);
            }
        }
    }
    __syncthreads();
#pragma unroll
    for (int it = 0; it < 8; it++) {
        int lin = it * 256 + tid;        // 0..2047
        int r   = lin >> 4;              // 0..127
        int c16 = lin & 15;              // 16B segment (128 fp16 = 16 segs)
        uint4 v = *(uint4*)(st + r * STG_STRIDE + c16 * 16);
        *(uint4*)(oh + (size_t)(m0 + r) * LDO + n0 + c16 * 8) = v;
    }
}

// ---------------------------------------------------------------------------
extern "C" void kernel_launch(void* const* d_in, const int* in_sizes, int n_in,
                              void* d_out, int out_size) {
    const float* x   = (const float*)d_in[0];
    const float* a   = (const float*)d_in[1];
    const float* W1  = (const float*)d_in[2];
    const float* b1  = (const float*)d_in[3];
    const float* Wmu = (const float*)d_in[4];
    const float* bmu = (const float*)d_in[5];
    const float* Wlv = (const float*)d_in[6];
    const float* blv = (const float*)d_in[7];
    float* out = (float*)d_out;

    cudaFuncSetAttribute(gemm_k<NNODE, 0, IND>,  cudaFuncAttributeMaxDynamicSharedMemorySize, GEMM_SMEM);
    cudaFuncSetAttribute(gemm_k<IND,   1, HIDD>, cudaFuncAttributeMaxDynamicSharedMemorySize, GEMM_SMEM);
    cudaFuncSetAttribute(gemm_k<HIDD,  3, LATD>, cudaFuncAttributeMaxDynamicSharedMemorySize, GEMM_SMEM);

    __half *ah, *xt, *h, *h1, *w1, *wc;
    cudaGetSymbolAddress((void**)&ah, g_ah);
    cudaGetSymbolAddress((void**)&xt, g_xt);
    cudaGetSymbolAddress((void**)&h,  g_h);
    cudaGetSymbolAddress((void**)&h1, g_h1);
    cudaGetSymbolAddress((void**)&w1, g_w1);
    cudaGetSymbolAddress((void**)&wc, g_wcat);

    // #1 adjacency -> fp16 + degree factors
    dsplit_a_kernel<<<TOK / 8, 256>>>(a);
    // #2 x transpose + d_j scale -> fp16
    split_xt_kernel<<<dim3(IND / 32, NNODE / 32, BB), dim3(32, 8)>>>(x);
    // #3 all weight conversions
    split_w_kernel<<<(W1_F4 + 2 * WHD_F4) / 256, 256>>>(W1, Wmu, Wlv);
    // #4 message passing GEMM (profiled launch): h = a_norm @ x
    gemm_k<NNODE, 0, IND><<<dim3(IND / 128, TOK / 128), 256, GEMM_SMEM>>>(
        ah, xt, (long)IND * NNODE, nullptr, h, nullptr, nullptr, x);
    // #5 h1 = relu(h @ W1^T + b1)
    gemm_k<IND, 1, HIDD><<<dim3(HIDD / 128, TOK / 128), 256, GEMM_SMEM>>>(
        h, w1, 0, nullptr, h1, b1, nullptr, nullptr);
    // #6 fused mu+logvar heads: one N=512 GEMM over [Wmu; Wlv]
    gemm_k<HIDD, 3, LATD><<<dim3((2 * LATD) / 128, TOK / 128), 256, GEMM_SMEM>>>(
        h1, wc, 0, out, nullptr, bmu, blv, nullptr);
}

// round 12
// speedup vs baseline: 2.6345x; 1.1274x over previous
#include <cuda_runtime.h>
#include <cuda_fp16.h>
#include <cstdint>

#define BB    64
#define NNODE 1024
#define IND   512
#define HIDD  1024
#define LATD  256
#define TOK   (BB * NNODE)   // 65536

// ---------------------------------------------------------------------------
// Scratch (device globals — allocation is forbidden)
// ---------------------------------------------------------------------------
__device__ float g_d[TOK];
__device__ __align__(16) __half g_ah[(size_t)BB * NNODE * NNODE];   // a, fp16
__device__ __align__(16) __half g_xt[(size_t)BB * IND * NNODE];     // d_j * x^T
__device__ __align__(16) __half g_h[(size_t)TOK * IND];
__device__ __align__(16) __half g_h1[(size_t)TOK * HIDD];
__device__ __align__(16) __half g_w1[HIDD * IND];
__device__ __align__(16) __half g_wcat[2 * LATD * HIDD];            // [Wmu; Wlv]

// ---------------------------------------------------------------------------
// helpers (baseline PTX only)
// ---------------------------------------------------------------------------
__device__ __forceinline__ uint32_t smem_u32(const void* p) {
    uint32_t a;
    asm("{ .reg .u64 t; cvta.to.shared.u64 t, %1; cvt.u32.u64 %0, t; }" : "=r"(a) : "l"(p));
    return a;
}
__device__ __forceinline__ void ldsm4(uint32_t addr, uint32_t* r) {
    asm volatile("ldmatrix.sync.aligned.m8n8.x4.shared.b16 {%0,%1,%2,%3}, [%4];"
                 : "=r"(r[0]), "=r"(r[1]), "=r"(r[2]), "=r"(r[3]) : "r"(addr));
}
__device__ __forceinline__ void mma16816(float* c, const uint32_t* a, const uint32_t* b) {
    asm volatile(
        "mma.sync.aligned.m16n8k16.row.col.f32.f16.f16.f32 "
        "{%0,%1,%2,%3}, {%4,%5,%6,%7}, {%8,%9}, {%0,%1,%2,%3};"
        : "+f"(c[0]), "+f"(c[1]), "+f"(c[2]), "+f"(c[3])
        : "r"(a[0]), "r"(a[1]), "r"(a[2]), "r"(a[3]), "r"(b[0]), "r"(b[1]));
}
__device__ __forceinline__ void cpasync16(uint32_t dst, const void* src) {
    asm volatile("cp.async.cg.shared.global [%0], [%1], 16;" :: "r"(dst), "l"(src) : "memory");
}
#define CP_COMMIT() asm volatile("cp.async.commit_group;" ::: "memory")
#define CP_WAIT0()  asm volatile("cp.async.wait_group 0;" ::: "memory")
#define CP_WAIT1()  asm volatile("cp.async.wait_group 1;" ::: "memory")

// ---------------------------------------------------------------------------
// Fused: a -> fp16 AND degree d = rsqrt(rowsum + 1 + 1e-8)
// ---------------------------------------------------------------------------
__global__ void __launch_bounds__(256) dsplit_a_kernel(const float* __restrict__ a) {
    int warp = (blockIdx.x * 256 + threadIdx.x) >> 5;
    int lane = threadIdx.x & 31;
    const float4* row = (const float4*)(a + (size_t)warp * NNODE);
    __half2* o = (__half2*)(g_ah + (size_t)warp * NNODE);
    float s = 0.f;
#pragma unroll
    for (int j = 0; j < 8; j++) {
        int i4 = lane + j * 32;
        float4 v = row[i4];
        s += v.x + v.y + v.z + v.w;
        o[2 * i4]     = __floats2half2_rn(v.x, v.y);
        o[2 * i4 + 1] = __floats2half2_rn(v.z, v.w);
    }
#pragma unroll
    for (int off = 16; off; off >>= 1) s += __shfl_xor_sync(0xffffffffu, s, off);
    if (lane == 0) g_d[warp] = rsqrtf(s + 1.0f + 1e-8f);
}

// ---------------------------------------------------------------------------
// Kernel: xt[b,c,j] = fp16(d[b,j] * x[b,j,c])  (transposed)
// ---------------------------------------------------------------------------
__global__ void __launch_bounds__(256) split_xt_kernel(const float* __restrict__ x) {
    __shared__ float t[32][33];
    int b  = blockIdx.z;
    int j0 = blockIdx.y * 32;
    int c0 = blockIdx.x * 32;
    int tx = threadIdx.x, ty = threadIdx.y;      // (32, 8)
#pragma unroll
    for (int k = 0; k < 4; k++) {
        int j = j0 + ty + k * 8;
        float dv = g_d[b * NNODE + j];
        t[ty + k * 8][tx] = x[((size_t)(b * NNODE + j)) * IND + c0 + tx] * dv;
    }
    __syncthreads();
#pragma unroll
    for (int k = 0; k < 4; k++) {
        int c = c0 + ty + k * 8;
        int j = j0 + tx;
        g_xt[((size_t)b * IND + c) * NNODE + j] = __float2half_rn(t[tx][ty + k * 8]);
    }
}

// ---------------------------------------------------------------------------
// All weight conversions (single fp16) in one kernel
// ---------------------------------------------------------------------------
#define W1_F4   (HIDD * IND / 4)          // 131072
#define WHD_F4  (LATD * HIDD / 4)         // 65536
__global__ void __launch_bounds__(256) split_w_kernel(const float* __restrict__ W1,
                                                      const float* __restrict__ Wmu,
                                                      const float* __restrict__ Wlv) {
    size_t i = (size_t)blockIdx.x * 256 + threadIdx.x;
    const float* src; __half* dst; size_t o;
    if (i < W1_F4)                 { src = W1;  dst = g_w1;   o = i; }
    else if (i < W1_F4 + WHD_F4)   { src = Wmu; dst = g_wcat; o = i - W1_F4; }
    else                           { src = Wlv; dst = g_wcat + (size_t)LATD * HIDD;
                                     o = i - W1_F4 - WHD_F4; }
    float4 v = ((const float4*)src)[o];
    ((__half2*)dst)[2 * o]     = __floats2half2_rn(v.x, v.y);
    ((__half2*)dst)[2 * o + 1] = __floats2half2_rn(v.z, v.w);
}

// ---------------------------------------------------------------------------
// Pure fp16 GEMM via mma.sync (HMMA): D[m,n] = sum_k A[m,k]*B[n,k]
// CTA tile 128x128, KC=64 (64 MMAs per barrier), 3-stage cp.async pipeline.
// SMEM rows 128B with swizzle seg' = (seg + row) & 7 (conflict-free for
// 16B staging stores and ldmatrix; invariant under +16-row warp steps).
// Buffer = A 16KB + B 16KB = 32KB; 3 buffers = 96KB; 2 CTAs/SM.
// EPI: 0 = message passing (d_m scale + d_m^2*x diag, fp16 out)
//      1 = bias + relu (fp16 out)
//      3 = dual-head bias (cols<256 -> mu else logvar), fp32 out
// ---------------------------------------------------------------------------
#define TILE_B 16384
#define BUF_B  32768
#define GEMM_SMEM 98304
#define STG_STRIDE 272      // (128+8) fp16 per row (epilogue restage)

template <int KDIM, int EPI, int LDO>
__global__ void __launch_bounds__(256, 2) gemm_k(
    const __half* __restrict__ A,
    const __half* __restrict__ B,
    long bstride,
    float* __restrict__ outf,
    __half* __restrict__ oh,
    const float* __restrict__ bias, const float* __restrict__ bias2,
    const float* __restrict__ xdiag)
{
    extern __shared__ char smem_raw[];
    const uint32_t sb  = smem_u32(smem_raw);
    const int tid  = threadIdx.x;
    const int wid  = tid >> 5;
    const int lane = tid & 31;
    const int n0   = blockIdx.x * 128;
    const int m0   = blockIdx.y * 128;
    const int wm   = wid & 3;       // 4 warps in M (32 rows)
    const int wn   = wid >> 2;      // 2 warps in N (64 cols)

    const __half* Bb = B + (bstride ? (long)(m0 >> 10) * bstride : 0);

    float acc[2][8][4];
#pragma unroll
    for (int i = 0; i < 2; i++)
#pragma unroll
        for (int j = 0; j < 8; j++)
#pragma unroll
            for (int k = 0; k < 4; k++) acc[i][j][k] = 0.f;

    // ldmatrix per-lane constants (128B rows; swizzle term = row & 7)
    const int a_row  = wm * 32 + (lane & 15);
    const int a_sw0  = (lane >> 4) + a_row;              // unit + row (mask at use)
    const uint32_t a_base = (uint32_t)(a_row * 128);
    const int b_row  = wn * 64 + ((lane >> 4) << 3) + (lane & 7);
    const int b_sw0  = ((lane >> 3) & 1) + b_row;
    const uint32_t b_base = (uint32_t)(b_row * 128);

    const int NC = KDIM / 64;

    auto stage = [&](int kk, uint32_t buf) {
        // A tile: 128 rows * 8 segs = 1024
#pragma unroll
        for (int i = 0; i < 4; i++) {
            int idx  = i * 256 + tid;
            int row  = idx >> 3;
            int seg  = idx & 7;
            uint32_t sw = (uint32_t)(((seg + row) & 7) << 4);
            cpasync16(buf + row * 128 + sw,
                      A + (size_t)(m0 + row) * KDIM + kk + seg * 8);
        }
        // B tile: 128 rows * 8 segs = 1024
#pragma unroll
        for (int i = 0; i < 4; i++) {
            int idx  = i * 256 + tid;
            int row  = idx >> 3;
            int seg  = idx & 7;
            uint32_t sw = (uint32_t)(((seg + row) & 7) << 4);
            cpasync16(buf + TILE_B + row * 128 + sw,
                      Bb + (size_t)(n0 + row) * KDIM + kk + seg * 8);
        }
        CP_COMMIT();
    };

    // prologue: two chunks in flight
    stage(0, sb);
    if (NC > 1) stage(64, sb + BUF_B);

    int bufidx = 0;
    for (int t = 0; t < NC; t++) {
        if (t == NC - 1) { CP_WAIT0(); } else { CP_WAIT1(); }
        __syncthreads();

        if (t + 2 < NC) {
            int nb = bufidx + 2; if (nb >= 3) nb -= 3;
            stage((t + 2) * 64, sb + (uint32_t)nb * BUF_B);
        }

        const uint32_t base = sb + (uint32_t)bufidx * BUF_B;
        if (++bufidx == 3) bufidx = 0;

#pragma unroll
        for (int ks = 0; ks < 4; ks++) {
            const uint32_t aswk = (uint32_t)(((a_sw0 + ks * 2) & 7) << 4);
            const uint32_t bswk = (uint32_t)(((b_sw0 + ks * 2) & 7) << 4);
            uint32_t ah[2][4];
#pragma unroll
            for (int tm = 0; tm < 2; tm++)
                ldsm4(base + a_base + tm * 2048 + aswk, ah[tm]);
#pragma unroll
            for (int tnp = 0; tnp < 4; tnp++) {
                uint32_t bh[4];
                ldsm4(base + TILE_B + b_base + tnp * 2048 + bswk, bh);
#pragma unroll
                for (int tm = 0; tm < 2; tm++)
#pragma unroll
                    for (int hf = 0; hf < 2; hf++)
                        mma16816(acc[tm][tnp * 2 + hf], ah[tm], bh + hf * 2);
            }
        }
    }

    if (EPI == 3) {
#pragma unroll
        for (int tm = 0; tm < 2; tm++)
#pragma unroll
            for (int hf = 0; hf < 2; hf++) {
                const int row = m0 + wm * 32 + tm * 16 + hf * 8 + (lane >> 2);
#pragma unroll
                for (int tn = 0; tn < 8; tn++) {
                    const int col = n0 + wn * 64 + tn * 8 + (lane & 3) * 2;
                    float v0 = acc[tm][tn][hf * 2 + 0];
                    float v1 = acc[tm][tn][hf * 2 + 1];
                    const float* bp = (col < LATD) ? (bias + col) : (bias2 + col - LATD);
                    float2 bv = *(const float2*)bp;
                    v0 += bv.x; v1 += bv.y;
                    float* dst = (col < LATD)
                        ? (outf + (size_t)row * LATD + col)
                        : (outf + (size_t)TOK * LATD + (size_t)row * LATD + (col - LATD));
                    *(float2*)dst = make_float2(v0, v1);
                }
            }
        return;
    }

    // EPI 0/1: epilogue math, SMEM restage (fp16), 16B/lane stores
    __syncthreads();
    char* st = smem_raw;                 // 128 * 272 = 34816 <= 98304
#pragma unroll
    for (int tm = 0; tm < 2; tm++) {
#pragma unroll
        for (int hf = 0; hf < 2; hf++) {
            const int rl = wm * 32 + tm * 16 + hf * 8 + (lane >> 2);
            const int row = m0 + rl;
            float di = 0.f, d2 = 0.f;
            if (EPI == 0) { di = g_d[row]; d2 = di * di; }
#pragma unroll
            for (int tn = 0; tn < 8; tn++) {
                const int cl = wn * 64 + tn * 8 + (lane & 3) * 2;
                float v0 = acc[tm][tn][hf * 2 + 0];
                float v1 = acc[tm][tn][hf * 2 + 1];
                if (EPI == 0) {
                    float2 xv = *(const float2*)(xdiag + (size_t)row * LDO + n0 + cl);
                    v0 = di * v0 + d2 * xv.x;
                    v1 = di * v1 + d2 * xv.y;
                } else {
                    float2 bv = *(const float2*)(bias + n0 + cl);
                    v0 = fmaxf(v0 + bv.x, 0.f);
                    v1 = fmaxf(v1 + bv.y, 0.f);
                }
                *(__half2*)(st + rl * STG_STRIDE + cl * 2) = __floats2half2_rn(v0, v1);
            }
        }
    }
    __syncthreads();
#pragma unroll
    for (int it = 0; it < 8; it++) {
        int lin = it * 256 + tid;        // 0..2047
        int r   = lin >> 4;              // 0..127
        int c16 = lin & 15;              // 16B segment (128 fp16 = 16 segs)
        uint4 v = *(uint4*)(st + r * STG_STRIDE + c16 * 16);
        *(uint4*)(oh + (size_t)(m0 + r) * LDO + n0 + c16 * 8) = v;
    }
}

// ---------------------------------------------------------------------------
extern "C" void kernel_launch(void* const* d_in, const int* in_sizes, int n_in,
                              void* d_out, int out_size) {
    const float* x   = (const float*)d_in[0];
    const float* a   = (const float*)d_in[1];
    const float* W1  = (const float*)d_in[2];
    const float* b1  = (const float*)d_in[3];
    const float* Wmu = (const float*)d_in[4];
    const float* bmu = (const float*)d_in[5];
    const float* Wlv = (const float*)d_in[6];
    const float* blv = (const float*)d_in[7];
    float* out = (float*)d_out;

    cudaFuncSetAttribute(gemm_k<NNODE, 0, IND>,  cudaFuncAttributeMaxDynamicSharedMemorySize, GEMM_SMEM);
    cudaFuncSetAttribute(gemm_k<IND,   1, HIDD>, cudaFuncAttributeMaxDynamicSharedMemorySize, GEMM_SMEM);
    cudaFuncSetAttribute(gemm_k<HIDD,  3, LATD>, cudaFuncAttributeMaxDynamicSharedMemorySize, GEMM_SMEM);

    __half *ah, *xt, *h, *h1, *w1, *wc;
    cudaGetSymbolAddress((void**)&ah, g_ah);
    cudaGetSymbolAddress((void**)&xt, g_xt);
    cudaGetSymbolAddress((void**)&h,  g_h);
    cudaGetSymbolAddress((void**)&h1, g_h1);
    cudaGetSymbolAddress((void**)&w1, g_w1);
    cudaGetSymbolAddress((void**)&wc, g_wcat);

    // #1 adjacency -> fp16 + degree factors
    dsplit_a_kernel<<<TOK / 8, 256>>>(a);
    // #2 x transpose + d_j scale -> fp16
    split_xt_kernel<<<dim3(IND / 32, NNODE / 32, BB), dim3(32, 8)>>>(x);
    // #3 all weight conversions
    split_w_kernel<<<(W1_F4 + 2 * WHD_F4) / 256, 256>>>(W1, Wmu, Wlv);
    // #4 message passing GEMM (profiled launch): h = a_norm @ x
    gemm_k<NNODE, 0, IND><<<dim3(IND / 128, TOK / 128), 256, GEMM_SMEM>>>(
        ah, xt, (long)IND * NNODE, nullptr, h, nullptr, nullptr, x);
    // #5 h1 = relu(h @ W1^T + b1)
    gemm_k<IND, 1, HIDD><<<dim3(HIDD / 128, TOK / 128), 256, GEMM_SMEM>>>(
        h, w1, 0, nullptr, h1, b1, nullptr, nullptr);
    // #6 fused mu+logvar heads: one N=512 GEMM over [Wmu; Wlv]
    gemm_k<HIDD, 3, LATD><<<dim3((2 * LATD) / 128, TOK / 128), 256, GEMM_SMEM>>>(
        h1, wc, 0, out, nullptr, bmu, blv, nullptr);
}